// round 3
// baseline (speedup 1.0000x reference)
#include <cuda_runtime.h>
#include <cfloat>

// Problem shape (fixed by reference): point_cloud [32, 262144, 3] fp32
static constexpr int NB       = 32;
static constexpr int NPTS     = 262144;
static constexpr int F_PER_B  = NPTS * 3;        // 786432 floats per batch
static constexpr int Q_PER_B  = F_PER_B / 4;     // 196608 float4 per batch
static constexpr int G_PER_B  = F_PER_B / 12;    // 65536 groups of 3 float4 (= 4 points)

static constexpr int THREADS  = 256;
static constexpr int BLOCKS1  = 32;              // pass-1 blocks per batch
static constexpr int GPB1     = G_PER_B / BLOCKS1;   // 2048 groups/block -> 8 iters/thread
static constexpr int BLOCKS2  = 64;              // pass-2 blocks per batch
static constexpr int GPB2     = G_PER_B / BLOCKS2;   // 1024 groups/block -> 4 iters/thread

// Per-(batch, coord) min/max scratch, encoded as order-preserving uint32.
// Re-initialized by init_kernel on every launch (graph-replay safe).
__device__ unsigned int g_umin[NB * 3];
__device__ unsigned int g_umax[NB * 3];

// Monotone float <-> uint mapping (no NaNs in this workload).
__device__ __forceinline__ unsigned int f2ord(float f) {
    unsigned int u = __float_as_uint(f);
    return (u & 0x80000000u) ? ~u : (u | 0x80000000u);
}
__device__ __forceinline__ float ord2f(unsigned int k) {
    return __uint_as_float((k & 0x80000000u) ? (k ^ 0x80000000u) : ~k);
}

__global__ void init_kernel() {
    int i = threadIdx.x;
    if (i < NB * 3) {
        g_umin[i] = 0xFFFFFFFFu;  // encodes +inf side
        g_umax[i] = 0u;           // encodes -inf side
    }
}

// Pass 1: per-batch per-coordinate min/max.
// Each "group" = 3 consecutive float4 = 12 floats = 4 points; component pattern
// over the 12 floats is statically 0,1,2,0,1,2,0,1,2,0,1,2.
__global__ void __launch_bounds__(THREADS)
minmax_kernel(const float4* __restrict__ p) {
    const int b = blockIdx.y;
    const float4* pb = p + (size_t)b * Q_PER_B;
    const int g0 = blockIdx.x * GPB1;

    float mn0 =  FLT_MAX, mn1 =  FLT_MAX, mn2 =  FLT_MAX;
    float mx0 = -FLT_MAX, mx1 = -FLT_MAX, mx2 = -FLT_MAX;

    #pragma unroll 4
    for (int g = g0 + threadIdx.x; g < g0 + GPB1; g += THREADS) {
        const float4 a = pb[3 * g + 0];
        const float4 bq = pb[3 * g + 1];
        const float4 c = pb[3 * g + 2];
        // comp0: a.x a.w bq.z c.y | comp1: a.y bq.x bq.w c.z | comp2: a.z bq.y c.x c.w
        mn0 = fminf(mn0, fminf(fminf(a.x, a.w),  fminf(bq.z, c.y)));
        mx0 = fmaxf(mx0, fmaxf(fmaxf(a.x, a.w),  fmaxf(bq.z, c.y)));
        mn1 = fminf(mn1, fminf(fminf(a.y, bq.x), fminf(bq.w, c.z)));
        mx1 = fmaxf(mx1, fmaxf(fmaxf(a.y, bq.x), fmaxf(bq.w, c.z)));
        mn2 = fminf(mn2, fminf(fminf(a.z, bq.y), fminf(c.x, c.w)));
        mx2 = fmaxf(mx2, fmaxf(fmaxf(a.z, bq.y), fmaxf(c.x, c.w)));
    }

    // Warp reduction
    #pragma unroll
    for (int off = 16; off > 0; off >>= 1) {
        mn0 = fminf(mn0, __shfl_xor_sync(0xFFFFFFFFu, mn0, off));
        mn1 = fminf(mn1, __shfl_xor_sync(0xFFFFFFFFu, mn1, off));
        mn2 = fminf(mn2, __shfl_xor_sync(0xFFFFFFFFu, mn2, off));
        mx0 = fmaxf(mx0, __shfl_xor_sync(0xFFFFFFFFu, mx0, off));
        mx1 = fmaxf(mx1, __shfl_xor_sync(0xFFFFFFFFu, mx1, off));
        mx2 = fmaxf(mx2, __shfl_xor_sync(0xFFFFFFFFu, mx2, off));
    }

    __shared__ float s[6][THREADS / 32];
    const int w = threadIdx.x >> 5, lane = threadIdx.x & 31;
    if (lane == 0) {
        s[0][w] = mn0; s[1][w] = mn1; s[2][w] = mn2;
        s[3][w] = mx0; s[4][w] = mx1; s[5][w] = mx2;
    }
    __syncthreads();

    if (threadIdx.x < 6) {
        const int i = threadIdx.x;
        float v = s[i][0];
        if (i < 3) {
            #pragma unroll
            for (int k = 1; k < THREADS / 32; k++) v = fminf(v, s[i][k]);
            atomicMin(&g_umin[b * 3 + i], f2ord(v));
        } else {
            #pragma unroll
            for (int k = 1; k < THREADS / 32; k++) v = fmaxf(v, s[i][k]);
            atomicMax(&g_umax[b * 3 + (i - 3)], f2ord(v));
        }
    }
}

// Pass 2: voxels = floor((p - min) * (1 / bin_width)), bin_width = (max - min) / 40
__global__ void __launch_bounds__(THREADS)
voxel_kernel(const float4* __restrict__ p, float4* __restrict__ out) {
    const int b = blockIdx.y;
    const size_t boff = (size_t)b * Q_PER_B;
    const float4* pb = p + boff;
    float4* ob = out + boff;

    // Per-batch constants (6 cached global loads + a handful of FLOPs per thread)
    const float mn0 = ord2f(g_umin[b * 3 + 0]);
    const float mn1 = ord2f(g_umin[b * 3 + 1]);
    const float mn2 = ord2f(g_umin[b * 3 + 2]);
    const float bw0 = (ord2f(g_umax[b * 3 + 0]) - mn0) / 40.0f;
    const float bw1 = (ord2f(g_umax[b * 3 + 1]) - mn1) / 40.0f;
    const float bw2 = (ord2f(g_umax[b * 3 + 2]) - mn2) / 40.0f;
    const float inv0 = 1.0f / bw0;
    const float inv1 = 1.0f / bw1;
    const float inv2 = 1.0f / bw2;

    const int g0 = blockIdx.x * GPB2;

    #pragma unroll 4
    for (int g = g0 + threadIdx.x; g < g0 + GPB2; g += THREADS) {
        const float4 a = pb[3 * g + 0];
        const float4 bq = pb[3 * g + 1];
        const float4 c = pb[3 * g + 2];

        float4 ra, rb, rc;
        ra.x = floorf((a.x  - mn0) * inv0);
        ra.y = floorf((a.y  - mn1) * inv1);
        ra.z = floorf((a.z  - mn2) * inv2);
        ra.w = floorf((a.w  - mn0) * inv0);
        rb.x = floorf((bq.x - mn1) * inv1);
        rb.y = floorf((bq.y - mn2) * inv2);
        rb.z = floorf((bq.z - mn0) * inv0);
        rb.w = floorf((bq.w - mn1) * inv1);
        rc.x = floorf((c.x  - mn2) * inv2);
        rc.y = floorf((c.y  - mn0) * inv0);
        rc.z = floorf((c.z  - mn1) * inv1);
        rc.w = floorf((c.w  - mn2) * inv2);

        ob[3 * g + 0] = ra;
        ob[3 * g + 1] = rb;
        ob[3 * g + 2] = rc;
    }
}

extern "C" void kernel_launch(void* const* d_in, const int* in_sizes, int n_in,
                              void* d_out, int out_size) {
    const float4* p = (const float4*)d_in[0];
    float4* o = (float4*)d_out;

    init_kernel<<<1, 128>>>();
    minmax_kernel<<<dim3(BLOCKS1, NB), THREADS>>>(p);
    voxel_kernel<<<dim3(BLOCKS2, NB), THREADS>>>(p, o);
}

// round 4
// speedup vs baseline: 1.0661x; 1.0661x over previous
#include <cuda_runtime.h>
#include <cfloat>

// Problem shape (fixed by reference): point_cloud [32, 262144, 3] fp32
static constexpr int NB       = 32;
static constexpr int NPTS     = 262144;
static constexpr int F_PER_B  = NPTS * 3;        // 786432 floats per batch
static constexpr int Q_PER_B  = F_PER_B / 4;     // 196608 float4 per batch
static constexpr int G_PER_B  = F_PER_B / 12;    // 65536 groups of 3 float4 (= 4 points)

static constexpr int THREADS  = 256;
static constexpr int BLOCKS1  = 32;              // pass-1 blocks per batch (== warp size, for the prologue reduce)
static constexpr int GPB1     = G_PER_B / BLOCKS1;   // 2048 groups/block -> 8 iters/thread
static constexpr int BLOCKS2  = 64;              // pass-2 blocks per batch
static constexpr int GPB2     = G_PER_B / BLOCKS2;   // 1024 groups/block -> 4 iters/thread

// Per-(batch, quantity, block) partials. Every slot is written unconditionally
// by pass 1 on every launch -> no init kernel, no atomics, graph-replay safe.
// Quantity index: 0..2 = min(x,y,z), 3..5 = max(x,y,z).
__device__ float g_part[NB][6][BLOCKS1];

// ───────────────────────── Pass 1: per-batch per-coord min/max partials ─────
// Each "group" = 3 consecutive float4 = 12 floats = 4 points; component
// pattern over the 12 floats is statically 0,1,2 repeated.
__global__ void __launch_bounds__(THREADS)
minmax_kernel(const float4* __restrict__ p) {
    const int b = blockIdx.y;
    const float4* pb = p + (size_t)b * Q_PER_B;
    const int g0 = blockIdx.x * GPB1;

    float mn0 =  FLT_MAX, mn1 =  FLT_MAX, mn2 =  FLT_MAX;
    float mx0 = -FLT_MAX, mx1 = -FLT_MAX, mx2 = -FLT_MAX;

    #pragma unroll 4
    for (int g = g0 + threadIdx.x; g < g0 + GPB1; g += THREADS) {
        const float4 a  = pb[3 * g + 0];
        const float4 bq = pb[3 * g + 1];
        const float4 c  = pb[3 * g + 2];
        // comp0: a.x a.w bq.z c.y | comp1: a.y bq.x bq.w c.z | comp2: a.z bq.y c.x c.w
        mn0 = fminf(mn0, fminf(fminf(a.x, a.w),  fminf(bq.z, c.y)));
        mx0 = fmaxf(mx0, fmaxf(fmaxf(a.x, a.w),  fmaxf(bq.z, c.y)));
        mn1 = fminf(mn1, fminf(fminf(a.y, bq.x), fminf(bq.w, c.z)));
        mx1 = fmaxf(mx1, fmaxf(fmaxf(a.y, bq.x), fmaxf(bq.w, c.z)));
        mn2 = fminf(mn2, fminf(fminf(a.z, bq.y), fminf(c.x, c.w)));
        mx2 = fmaxf(mx2, fmaxf(fmaxf(a.z, bq.y), fmaxf(c.x, c.w)));
    }

    // Warp reduction
    #pragma unroll
    for (int off = 16; off > 0; off >>= 1) {
        mn0 = fminf(mn0, __shfl_xor_sync(0xFFFFFFFFu, mn0, off));
        mn1 = fminf(mn1, __shfl_xor_sync(0xFFFFFFFFu, mn1, off));
        mn2 = fminf(mn2, __shfl_xor_sync(0xFFFFFFFFu, mn2, off));
        mx0 = fmaxf(mx0, __shfl_xor_sync(0xFFFFFFFFu, mx0, off));
        mx1 = fmaxf(mx1, __shfl_xor_sync(0xFFFFFFFFu, mx1, off));
        mx2 = fmaxf(mx2, __shfl_xor_sync(0xFFFFFFFFu, mx2, off));
    }

    __shared__ float s[6][THREADS / 32];
    const int w = threadIdx.x >> 5, lane = threadIdx.x & 31;
    if (lane == 0) {
        s[0][w] = mn0; s[1][w] = mn1; s[2][w] = mn2;
        s[3][w] = mx0; s[4][w] = mx1; s[5][w] = mx2;
    }
    __syncthreads();

    if (threadIdx.x < 6) {
        const int i = threadIdx.x;
        float v = s[i][0];
        if (i < 3) {
            #pragma unroll
            for (int k = 1; k < THREADS / 32; k++) v = fminf(v, s[i][k]);
        } else {
            #pragma unroll
            for (int k = 1; k < THREADS / 32; k++) v = fmaxf(v, s[i][k]);
        }
        g_part[b][i][blockIdx.x] = v;   // unconditional write -> no init needed
    }
}

// ───────────────────────── Pass 2: voxels = floor((p - min) / bin_width) ────
// Streaming cache hints: input is dead after this read (__ldcs), output is
// never re-read (__stcs) -> keep pass-1's L2 footprint from being evicted
// by write-allocates, so pass-2 reads stay L2 hits.
__global__ void __launch_bounds__(THREADS)
voxel_kernel(const float4* __restrict__ p, float4* __restrict__ out) {
    const int b = blockIdx.y;

    // Prologue: warps 0..5 each reduce the 32 per-block partials for one
    // quantity (lane l reads g_part[b][w][l] -> fully coalesced).
    __shared__ float cst[6];
    {
        const int w = threadIdx.x >> 5, lane = threadIdx.x & 31;
        if (w < 6) {
            float v = g_part[b][w][lane];
            if (w < 3) {
                #pragma unroll
                for (int off = 16; off > 0; off >>= 1)
                    v = fminf(v, __shfl_xor_sync(0xFFFFFFFFu, v, off));
            } else {
                #pragma unroll
                for (int off = 16; off > 0; off >>= 1)
                    v = fmaxf(v, __shfl_xor_sync(0xFFFFFFFFu, v, off));
            }
            if (lane == 0) cst[w] = v;
        }
    }
    __syncthreads();

    const float mn0 = cst[0], mn1 = cst[1], mn2 = cst[2];
    // Same RN division by 40 as the reference, then reciprocal-multiply per point.
    const float inv0 = 1.0f / ((cst[3] - mn0) / 40.0f);
    const float inv1 = 1.0f / ((cst[4] - mn1) / 40.0f);
    const float inv2 = 1.0f / ((cst[5] - mn2) / 40.0f);

    const size_t boff = (size_t)b * Q_PER_B;
    const float4* pb = p + boff;
    float4* ob = out + boff;
    const int g0 = blockIdx.x * GPB2;

    #pragma unroll 4
    for (int g = g0 + threadIdx.x; g < g0 + GPB2; g += THREADS) {
        const float4 a  = __ldcs(&pb[3 * g + 0]);
        const float4 bq = __ldcs(&pb[3 * g + 1]);
        const float4 c  = __ldcs(&pb[3 * g + 2]);

        float4 ra, rb, rc;
        ra.x = floorf((a.x  - mn0) * inv0);
        ra.y = floorf((a.y  - mn1) * inv1);
        ra.z = floorf((a.z  - mn2) * inv2);
        ra.w = floorf((a.w  - mn0) * inv0);
        rb.x = floorf((bq.x - mn1) * inv1);
        rb.y = floorf((bq.y - mn2) * inv2);
        rb.z = floorf((bq.z - mn0) * inv0);
        rb.w = floorf((bq.w - mn1) * inv1);
        rc.x = floorf((c.x  - mn2) * inv2);
        rc.y = floorf((c.y  - mn0) * inv0);
        rc.z = floorf((c.z  - mn1) * inv1);
        rc.w = floorf((c.w  - mn2) * inv2);

        __stcs(&ob[3 * g + 0], ra);
        __stcs(&ob[3 * g + 1], rb);
        __stcs(&ob[3 * g + 2], rc);
    }
}

extern "C" void kernel_launch(void* const* d_in, const int* in_sizes, int n_in,
                              void* d_out, int out_size) {
    const float4* p = (const float4*)d_in[0];
    float4* o = (float4*)d_out;

    minmax_kernel<<<dim3(BLOCKS1, NB), THREADS>>>(p);
    voxel_kernel<<<dim3(BLOCKS2, NB), THREADS>>>(p, o);
}

// round 5
// speedup vs baseline: 1.3596x; 1.2753x over previous
#include <cuda_runtime.h>
#include <cfloat>

// Problem shape (fixed by reference): point_cloud [32, 262144, 3] fp32
static constexpr int NB       = 32;
static constexpr int NPTS     = 262144;
static constexpr int F_PER_B  = NPTS * 3;        // 786432 floats per batch
static constexpr int Q_PER_B  = F_PER_B / 4;     // 196608 float4 per batch

static constexpr int THREADS  = 256;
static constexpr int BLOCKS1  = 32;              // pass-1 blocks/batch (== warp size for prologue reduce)
static constexpr int CHUNK1   = Q_PER_B / BLOCKS1;   // 6144 float4/block -> 24 loads/thread
static constexpr int BLOCKS2  = 64;              // pass-2 blocks/batch
static constexpr int CHUNK2   = Q_PER_B / BLOCKS2;   // 3072 float4/block -> 12 loads/thread

// Per-(batch, quantity, block) partials; every slot written unconditionally
// each launch -> no init kernel, no atomics, graph-replay safe.
// Quantity: 0..2 = min(x,y,z), 3..5 = max(x,y,z).
__device__ float g_part[NB][6][BLOCKS1];

// Component bookkeeping: float4 at index idx has components
// ((idx)%3, (idx+1)%3, (idx+2)%3, (idx)%3). Block bases are multiples of 3
// and the per-iteration stride is THREADS=256 ≡ 1 (mod 3), so with
// r = tid%3 the float4 loaded at unrolled sub-iter u has leading component
// (r+u)%3. All selection is static after pre-rotating constants by r.

// ───────────────── Pass 1: per-batch per-coord min/max partials ─────────────
__global__ void __launch_bounds__(THREADS)
minmax_kernel(const float4* __restrict__ p) {
    const int b = blockIdx.y;
    const float4* pb = p + (size_t)b * Q_PER_B + blockIdx.x * CHUNK1;
    const int tid = threadIdx.x;
    const int r = tid % 3;

    // A[s] accumulates component (r+s)%3
    float mnA0 =  FLT_MAX, mnA1 =  FLT_MAX, mnA2 =  FLT_MAX;
    float mxA0 = -FLT_MAX, mxA1 = -FLT_MAX, mxA2 = -FLT_MAX;

    #pragma unroll 2
    for (int ko = 0; ko < CHUNK1 / (3 * THREADS); ko++) {   // 8 outer iters
        const float4 a = pb[(ko * 3 + 0) * THREADS + tid];  // coalesced
        const float4 d = pb[(ko * 3 + 1) * THREADS + tid];
        const float4 c = pb[(ko * 3 + 2) * THREADS + tid];
        // u=0: comps (A0,A1,A2,A0)
        mnA0 = fminf(mnA0, fminf(a.x, a.w)); mxA0 = fmaxf(mxA0, fmaxf(a.x, a.w));
        mnA1 = fminf(mnA1, a.y);             mxA1 = fmaxf(mxA1, a.y);
        mnA2 = fminf(mnA2, a.z);             mxA2 = fmaxf(mxA2, a.z);
        // u=1: comps (A1,A2,A0,A1)
        mnA1 = fminf(mnA1, fminf(d.x, d.w)); mxA1 = fmaxf(mxA1, fmaxf(d.x, d.w));
        mnA2 = fminf(mnA2, d.y);             mxA2 = fmaxf(mxA2, d.y);
        mnA0 = fminf(mnA0, d.z);             mxA0 = fmaxf(mxA0, d.z);
        // u=2: comps (A2,A0,A1,A2)
        mnA2 = fminf(mnA2, fminf(c.x, c.w)); mxA2 = fmaxf(mxA2, fmaxf(c.x, c.w));
        mnA0 = fminf(mnA0, c.y);             mxA0 = fmaxf(mxA0, c.y);
        mnA1 = fminf(mnA1, c.z);             mxA1 = fmaxf(mxA1, c.z);
    }

    // Un-rotate: comp c lives in slot (c - r + 3) % 3
    float mn0, mn1, mn2, mx0, mx1, mx2;
    if (r == 0)      { mn0 = mnA0; mn1 = mnA1; mn2 = mnA2; mx0 = mxA0; mx1 = mxA1; mx2 = mxA2; }
    else if (r == 1) { mn0 = mnA2; mn1 = mnA0; mn2 = mnA1; mx0 = mxA2; mx1 = mxA0; mx2 = mxA1; }
    else             { mn0 = mnA1; mn1 = mnA2; mn2 = mnA0; mx0 = mxA1; mx1 = mxA2; mx2 = mxA0; }

    // Warp reduction
    #pragma unroll
    for (int off = 16; off > 0; off >>= 1) {
        mn0 = fminf(mn0, __shfl_xor_sync(0xFFFFFFFFu, mn0, off));
        mn1 = fminf(mn1, __shfl_xor_sync(0xFFFFFFFFu, mn1, off));
        mn2 = fminf(mn2, __shfl_xor_sync(0xFFFFFFFFu, mn2, off));
        mx0 = fmaxf(mx0, __shfl_xor_sync(0xFFFFFFFFu, mx0, off));
        mx1 = fmaxf(mx1, __shfl_xor_sync(0xFFFFFFFFu, mx1, off));
        mx2 = fmaxf(mx2, __shfl_xor_sync(0xFFFFFFFFu, mx2, off));
    }

    __shared__ float s[6][THREADS / 32];
    const int w = tid >> 5, lane = tid & 31;
    if (lane == 0) {
        s[0][w] = mn0; s[1][w] = mn1; s[2][w] = mn2;
        s[3][w] = mx0; s[4][w] = mx1; s[5][w] = mx2;
    }
    __syncthreads();

    if (tid < 6) {
        float v = s[tid][0];
        if (tid < 3) {
            #pragma unroll
            for (int k = 1; k < THREADS / 32; k++) v = fminf(v, s[tid][k]);
        } else {
            #pragma unroll
            for (int k = 1; k < THREADS / 32; k++) v = fmaxf(v, s[tid][k]);
        }
        g_part[b][tid][blockIdx.x] = v;
    }
}

// ───────────────── Pass 2: voxels = floor((p - min) / bin_width) ────────────
__global__ void __launch_bounds__(THREADS)
voxel_kernel(const float4* __restrict__ p, float4* __restrict__ out) {
    const int b = blockIdx.y;
    const int tid = threadIdx.x;

    // Prologue: warps 0..5 each reduce the 32 per-block partials for one quantity.
    __shared__ float cst[6];
    {
        const int w = tid >> 5, lane = tid & 31;
        if (w < 6) {
            float v = g_part[b][w][lane];
            if (w < 3) {
                #pragma unroll
                for (int off = 16; off > 0; off >>= 1)
                    v = fminf(v, __shfl_xor_sync(0xFFFFFFFFu, v, off));
            } else {
                #pragma unroll
                for (int off = 16; off > 0; off >>= 1)
                    v = fmaxf(v, __shfl_xor_sync(0xFFFFFFFFu, v, off));
            }
            if (lane == 0) cst[w] = v;
        }
    }
    __syncthreads();

    // Per-component constants, same RN division by 40 as reference, then
    // reciprocal-multiply per point (rel err << 1e-3 threshold).
    const float mnc[3]  = { cst[0], cst[1], cst[2] };
    const float invc[3] = { 1.0f / ((cst[3] - cst[0]) / 40.0f),
                            1.0f / ((cst[4] - cst[1]) / 40.0f),
                            1.0f / ((cst[5] - cst[2]) / 40.0f) };

    // Pre-rotate by r = tid % 3: R_s covers component (r+s)%3.
    const int r = tid % 3;
    const float mn_0 = mnc[r], mn_1 = mnc[(r + 1) % 3], mn_2 = mnc[(r + 2) % 3];
    const float iv_0 = invc[r], iv_1 = invc[(r + 1) % 3], iv_2 = invc[(r + 2) % 3];

    const size_t base = (size_t)b * Q_PER_B + blockIdx.x * CHUNK2;
    const float4* pb = p + base;
    float4* ob = out + base;

    #pragma unroll 2
    for (int ko = 0; ko < CHUNK2 / (3 * THREADS); ko++) {   // 4 outer iters
        const float4 a = __ldcs(&pb[(ko * 3 + 0) * THREADS + tid]);  // coalesced
        const float4 d = __ldcs(&pb[(ko * 3 + 1) * THREADS + tid]);
        const float4 c = __ldcs(&pb[(ko * 3 + 2) * THREADS + tid]);

        float4 ra, rd, rc;
        // u=0: comps (0,1,2,0)
        ra.x = floorf((a.x - mn_0) * iv_0);
        ra.y = floorf((a.y - mn_1) * iv_1);
        ra.z = floorf((a.z - mn_2) * iv_2);
        ra.w = floorf((a.w - mn_0) * iv_0);
        // u=1: comps (1,2,0,1)
        rd.x = floorf((d.x - mn_1) * iv_1);
        rd.y = floorf((d.y - mn_2) * iv_2);
        rd.z = floorf((d.z - mn_0) * iv_0);
        rd.w = floorf((d.w - mn_1) * iv_1);
        // u=2: comps (2,0,1,2)
        rc.x = floorf((c.x - mn_2) * iv_2);
        rc.y = floorf((c.y - mn_0) * iv_0);
        rc.z = floorf((c.z - mn_1) * iv_1);
        rc.w = floorf((c.w - mn_2) * iv_2);

        __stcs(&ob[(ko * 3 + 0) * THREADS + tid], ra);
        __stcs(&ob[(ko * 3 + 1) * THREADS + tid], rd);
        __stcs(&ob[(ko * 3 + 2) * THREADS + tid], rc);
    }
}

extern "C" void kernel_launch(void* const* d_in, const int* in_sizes, int n_in,
                              void* d_out, int out_size) {
    const float4* p = (const float4*)d_in[0];
    float4* o = (float4*)d_out;

    minmax_kernel<<<dim3(BLOCKS1, NB), THREADS>>>(p);
    voxel_kernel<<<dim3(BLOCKS2, NB), THREADS>>>(p, o);
}